// round 2
// baseline (speedup 1.0000x reference)
#include <cuda_runtime.h>
#include <cuda_bf16.h>
#include <math.h>

// Problem constants (from reference_code)
#define VOCAB  50257
#define DMODEL 1024
#define SEQ    2048
#define BSZ    2
#define ROWS   (BSZ * SEQ)   // 4096

// GEMM tiling
#define BM 128
#define BN 128
#define BK 16
#define TM 8
#define TN 8
#define THREADS 256
#define PAD 132   // smem row stride (floats): multiple of 4 for float4, avoids worst bank conflicts

// Scratch (no device allocations allowed -> __device__ globals)
__device__ float g_nll[ROWS];
__device__ int   g_correct[ROWS];

// -----------------------------------------------------------------------------
// GEMM: C[m, n] = sum_k A[m,k] * W[n,k]
// A: [ROWS, DMODEL] row-major, W: [VOCAB, DMODEL] row-major, C: [ROWS, VOCAB]
// 128x128 tile, BK=16, 256 threads, 8x8 per thread, gmem->reg prefetch double buffer.
// -----------------------------------------------------------------------------
__global__ __launch_bounds__(THREADS, 2)
void gemm_kernel(const float* __restrict__ A, const float* __restrict__ W,
                 float* __restrict__ C)
{
    __shared__ float As[BK][PAD];   // As[k][m]
    __shared__ float Bs[BK][PAD];   // Bs[k][n]

    const int n0  = blockIdx.x * BN;
    const int m0  = blockIdx.y * BM;
    const int tid = threadIdx.x;
    const int tx  = tid & 15;    // 0..15 -> n direction
    const int ty  = tid >> 4;    // 0..15 -> m direction

    // loader mapping: 4 threads per row, 2 passes of 64 rows
    const int lrow = tid >> 2;        // 0..63
    const int lcol = (tid & 3) * 4;   // 0,4,8,12

    float acc[TM][TN];
#pragma unroll
    for (int i = 0; i < TM; i++)
#pragma unroll
        for (int j = 0; j < TN; j++) acc[i][j] = 0.f;

    float4 pa[2], pb[2];

    const int KT = DMODEL / BK;   // 64 k-tiles

    // ---- load tile 0 into regs ----
#pragma unroll
    for (int p = 0; p < 2; p++) {
        const int ar = m0 + lrow + p * 64;
        pa[p] = *reinterpret_cast<const float4*>(&A[(size_t)ar * DMODEL + lcol]);
        const int br = n0 + lrow + p * 64;
        if (br < VOCAB)
            pb[p] = *reinterpret_cast<const float4*>(&W[(size_t)br * DMODEL + lcol]);
        else
            pb[p] = make_float4(0.f, 0.f, 0.f, 0.f);
    }
    // regs -> smem (transposed)
#pragma unroll
    for (int p = 0; p < 2; p++) {
        const int r = lrow + p * 64;
        As[lcol + 0][r] = pa[p].x; As[lcol + 1][r] = pa[p].y;
        As[lcol + 2][r] = pa[p].z; As[lcol + 3][r] = pa[p].w;
        Bs[lcol + 0][r] = pb[p].x; Bs[lcol + 1][r] = pb[p].y;
        Bs[lcol + 2][r] = pb[p].z; Bs[lcol + 3][r] = pb[p].w;
    }
    __syncthreads();

    for (int kt = 0; kt < KT; kt++) {
        // prefetch next k-tile into regs while computing current
        if (kt + 1 < KT) {
            const int k0 = (kt + 1) * BK;
#pragma unroll
            for (int p = 0; p < 2; p++) {
                const int ar = m0 + lrow + p * 64;
                pa[p] = *reinterpret_cast<const float4*>(&A[(size_t)ar * DMODEL + k0 + lcol]);
                const int br = n0 + lrow + p * 64;
                if (br < VOCAB)
                    pb[p] = *reinterpret_cast<const float4*>(&W[(size_t)br * DMODEL + k0 + lcol]);
                else
                    pb[p] = make_float4(0.f, 0.f, 0.f, 0.f);
            }
        }

        // compute current tile
#pragma unroll
        for (int k = 0; k < BK; k++) {
            float a[TM], b[TN];
            float4 t;
            t = *reinterpret_cast<const float4*>(&As[k][ty * TM]);
            a[0] = t.x; a[1] = t.y; a[2] = t.z; a[3] = t.w;
            t = *reinterpret_cast<const float4*>(&As[k][ty * TM + 4]);
            a[4] = t.x; a[5] = t.y; a[6] = t.z; a[7] = t.w;
            t = *reinterpret_cast<const float4*>(&Bs[k][tx * TN]);
            b[0] = t.x; b[1] = t.y; b[2] = t.z; b[3] = t.w;
            t = *reinterpret_cast<const float4*>(&Bs[k][tx * TN + 4]);
            b[4] = t.x; b[5] = t.y; b[6] = t.z; b[7] = t.w;
#pragma unroll
            for (int i = 0; i < TM; i++)
#pragma unroll
                for (int j = 0; j < TN; j++)
                    acc[i][j] = fmaf(a[i], b[j], acc[i][j]);
        }

        __syncthreads();
        if (kt + 1 < KT) {
#pragma unroll
            for (int p = 0; p < 2; p++) {
                const int r = lrow + p * 64;
                As[lcol + 0][r] = pa[p].x; As[lcol + 1][r] = pa[p].y;
                As[lcol + 2][r] = pa[p].z; As[lcol + 3][r] = pa[p].w;
                Bs[lcol + 0][r] = pb[p].x; Bs[lcol + 1][r] = pb[p].y;
                Bs[lcol + 2][r] = pb[p].z; Bs[lcol + 3][r] = pb[p].w;
            }
            __syncthreads();
        }
    }

    // epilogue: scalar stores (VOCAB=50257 is odd -> rows not 16B aligned)
#pragma unroll
    for (int i = 0; i < TM; i++) {
        const int m = m0 + ty * TM + i;
        float* crow = C + (size_t)m * VOCAB;
#pragma unroll
        for (int j = 0; j < TN; j++) {
            const int n = n0 + tx * TN + j;
            if (n < VOCAB) crow[n] = acc[i][j];
        }
    }
}

// -----------------------------------------------------------------------------
// Per-row: online log-sum-exp + argmax + target logit -> nll, correct flag
// -----------------------------------------------------------------------------
__global__ void row_stats_kernel(const float* __restrict__ C,
                                 const long long* __restrict__ target)
{
    const int r   = blockIdx.x;
    const int tid = threadIdx.x;
    const float* row = C + (size_t)r * VOCAB;

    float m = -INFINITY, s = 0.f;
    float av = -INFINITY; int ai = VOCAB;

    for (int i = tid; i < VOCAB; i += blockDim.x) {
        const float x = row[i];
        if (x > av || (x == av && i < ai)) { av = x; ai = i; }
        if (x > m) { s = s * expf(m - x) + 1.f; m = x; }
        else       { s += expf(x - m); }
    }

    __shared__ float sm[256], ss[256], sav[256];
    __shared__ int   sai[256];
    sm[tid] = m; ss[tid] = s; sav[tid] = av; sai[tid] = ai;
    __syncthreads();

    for (int off = 128; off > 0; off >>= 1) {
        if (tid < off) {
            const float m2 = sm[tid + off], s2 = ss[tid + off];
            const float M  = fmaxf(sm[tid], m2);
            ss[tid] = ss[tid] * expf(sm[tid] - M) + s2 * expf(m2 - M);
            sm[tid] = M;
            const float av2 = sav[tid + off]; const int ai2 = sai[tid + off];
            if (av2 > sav[tid] || (av2 == sav[tid] && ai2 < sai[tid])) {
                sav[tid] = av2; sai[tid] = ai2;
            }
        }
        __syncthreads();
    }

    if (tid == 0) {
        const int t  = (int)target[r];
        const float xt = row[t];
        g_nll[r]     = (logf(ss[0]) + sm[0]) - xt;
        g_correct[r] = (sai[0] == t) ? 1 : 0;
    }
}

// -----------------------------------------------------------------------------
// Final scalars: loss, token_accuracy, string_accuracy
// -----------------------------------------------------------------------------
__global__ void finalize_kernel(const int* __restrict__ mask,
                                float* __restrict__ out, int n_scalars)
{
    __shared__ float s_lo[256], s_cn[256], s_tk[256];
    __shared__ int   s_seq[BSZ];
    const int tid = threadIdx.x;
    if (tid < BSZ) s_seq[tid] = 1;
    __syncthreads();

    float lo = 0.f, cn = 0.f, tk = 0.f;
    for (int r = tid; r < ROWS; r += 256) {
        const int mk  = mask[r];
        const int cor = g_correct[r];
        if (mk) {
            lo += g_nll[r];
            cn += 1.f;
            tk += (float)cor;
            if (!cor) atomicAnd(&s_seq[r / SEQ], 0);
        }
    }
    s_lo[tid] = lo; s_cn[tid] = cn; s_tk[tid] = tk;
    __syncthreads();

    for (int off = 128; off > 0; off >>= 1) {
        if (tid < off) {
            s_lo[tid] += s_lo[tid + off];
            s_cn[tid] += s_cn[tid + off];
            s_tk[tid] += s_tk[tid + off];
        }
        __syncthreads();
    }

    if (tid == 0) {
        const float nvalid = s_cn[0];
        if (n_scalars >= 1) out[0] = s_lo[0] / nvalid;   // loss
        if (n_scalars >= 2) out[1] = s_tk[0] / nvalid;   // token_accuracy
        if (n_scalars >= 3) {
            float sacc = 0.f;
            for (int b = 0; b < BSZ; b++) sacc += (float)s_seq[b];
            out[2] = sacc / (float)BSZ;                  // string_accuracy
        }
    }
}

// -----------------------------------------------------------------------------
// Entry point. Inputs (metadata order): logits f32, target i64, mask i32, W f32.
// Output layout decided from out_size (defensive: never write OOB):
//   out_size >= 3 + ROWS*VOCAB : [loss, tok_acc, str_acc, tokens...]
//   out_size >= ROWS*VOCAB     : [tokens...] (scalars don't fit -> skip)
//   else                       : scalars only (tokens not representable; still
//                                need them transiently -> reuse nothing, skip)
// -----------------------------------------------------------------------------
extern "C" void kernel_launch(void* const* d_in, const int* in_sizes, int n_in,
                              void* d_out, int out_size)
{
    const float*     logits = (const float*)d_in[0];
    const long long* target = (const long long*)d_in[1];
    const int*       mask   = (const int*)d_in[2];
    const float*     W      = (const float*)d_in[3];

    float* out = (float*)d_out;
    const long long NTOK = (long long)ROWS * VOCAB;

    float* tokens;
    float* scalars;
    int n_scalars;
    if ((long long)out_size >= NTOK + 3) {
        scalars = out; n_scalars = (int)((long long)out_size - NTOK);
        if (n_scalars > 3) n_scalars = 3;
        tokens = out + n_scalars;
    } else if ((long long)out_size >= NTOK) {
        scalars = out; n_scalars = 0;
        tokens  = out;
    } else {
        // No room for the token matrix at all; nothing safe to do for it.
        // (Should not happen given the reference returns evaluate_tokens.)
        return;
    }

    dim3 grid((VOCAB + BN - 1) / BN, ROWS / BM);
    gemm_kernel<<<grid, THREADS>>>(logits, W, tokens);
    row_stats_kernel<<<ROWS, 256>>>(tokens, target);
    if (n_scalars > 0)
        finalize_kernel<<<1, 256>>>(mask, scalars, n_scalars);
}

// round 3
// speedup vs baseline: 1.0002x; 1.0002x over previous
#include <cuda_runtime.h>
#include <cuda_bf16.h>
#include <math.h>

// Problem constants (from reference_code)
#define VOCAB  50257
#define DMODEL 1024
#define SEQ    2048
#define BSZ    2
#define ROWS   (BSZ * SEQ)   // 4096

// GEMM tiling
#define BM 128
#define BN 128
#define BK 16
#define TM 8
#define TN 8
#define THREADS 256
#define PAD 132   // smem row stride (floats): multiple of 4 for float4, avoids worst bank conflicts

// Scratch (no device allocations allowed -> __device__ globals)
__device__ float g_nll[ROWS];
__device__ int   g_correct[ROWS];

// -----------------------------------------------------------------------------
// GEMM: C[m, n] = sum_k A[m,k] * W[n,k]
// A: [ROWS, DMODEL] row-major, W: [VOCAB, DMODEL] row-major, C: [ROWS, VOCAB]
// 128x128 tile, BK=16, 256 threads, 8x8 per thread, gmem->reg prefetch double buffer.
// -----------------------------------------------------------------------------
__global__ __launch_bounds__(THREADS, 2)
void gemm_kernel(const float* __restrict__ A, const float* __restrict__ W,
                 float* __restrict__ C)
{
    __shared__ float As[BK][PAD];   // As[k][m]
    __shared__ float Bs[BK][PAD];   // Bs[k][n]

    const int n0  = blockIdx.x * BN;
    const int m0  = blockIdx.y * BM;
    const int tid = threadIdx.x;
    const int tx  = tid & 15;    // 0..15 -> n direction
    const int ty  = tid >> 4;    // 0..15 -> m direction

    // loader mapping: 4 threads per row, 2 passes of 64 rows
    const int lrow = tid >> 2;        // 0..63
    const int lcol = (tid & 3) * 4;   // 0,4,8,12

    float acc[TM][TN];
#pragma unroll
    for (int i = 0; i < TM; i++)
#pragma unroll
        for (int j = 0; j < TN; j++) acc[i][j] = 0.f;

    float4 pa[2], pb[2];

    const int KT = DMODEL / BK;   // 64 k-tiles

    // ---- load tile 0 into regs ----
#pragma unroll
    for (int p = 0; p < 2; p++) {
        const int ar = m0 + lrow + p * 64;
        pa[p] = *reinterpret_cast<const float4*>(&A[(size_t)ar * DMODEL + lcol]);
        const int br = n0 + lrow + p * 64;
        if (br < VOCAB)
            pb[p] = *reinterpret_cast<const float4*>(&W[(size_t)br * DMODEL + lcol]);
        else
            pb[p] = make_float4(0.f, 0.f, 0.f, 0.f);
    }
    // regs -> smem (transposed)
#pragma unroll
    for (int p = 0; p < 2; p++) {
        const int r = lrow + p * 64;
        As[lcol + 0][r] = pa[p].x; As[lcol + 1][r] = pa[p].y;
        As[lcol + 2][r] = pa[p].z; As[lcol + 3][r] = pa[p].w;
        Bs[lcol + 0][r] = pb[p].x; Bs[lcol + 1][r] = pb[p].y;
        Bs[lcol + 2][r] = pb[p].z; Bs[lcol + 3][r] = pb[p].w;
    }
    __syncthreads();

    for (int kt = 0; kt < KT; kt++) {
        // prefetch next k-tile into regs while computing current
        if (kt + 1 < KT) {
            const int k0 = (kt + 1) * BK;
#pragma unroll
            for (int p = 0; p < 2; p++) {
                const int ar = m0 + lrow + p * 64;
                pa[p] = *reinterpret_cast<const float4*>(&A[(size_t)ar * DMODEL + k0 + lcol]);
                const int br = n0 + lrow + p * 64;
                if (br < VOCAB)
                    pb[p] = *reinterpret_cast<const float4*>(&W[(size_t)br * DMODEL + k0 + lcol]);
                else
                    pb[p] = make_float4(0.f, 0.f, 0.f, 0.f);
            }
        }

        // compute current tile
#pragma unroll
        for (int k = 0; k < BK; k++) {
            float a[TM], b[TN];
            float4 t;
            t = *reinterpret_cast<const float4*>(&As[k][ty * TM]);
            a[0] = t.x; a[1] = t.y; a[2] = t.z; a[3] = t.w;
            t = *reinterpret_cast<const float4*>(&As[k][ty * TM + 4]);
            a[4] = t.x; a[5] = t.y; a[6] = t.z; a[7] = t.w;
            t = *reinterpret_cast<const float4*>(&Bs[k][tx * TN]);
            b[0] = t.x; b[1] = t.y; b[2] = t.z; b[3] = t.w;
            t = *reinterpret_cast<const float4*>(&Bs[k][tx * TN + 4]);
            b[4] = t.x; b[5] = t.y; b[6] = t.z; b[7] = t.w;
#pragma unroll
            for (int i = 0; i < TM; i++)
#pragma unroll
                for (int j = 0; j < TN; j++)
                    acc[i][j] = fmaf(a[i], b[j], acc[i][j]);
        }

        __syncthreads();
        if (kt + 1 < KT) {
#pragma unroll
            for (int p = 0; p < 2; p++) {
                const int r = lrow + p * 64;
                As[lcol + 0][r] = pa[p].x; As[lcol + 1][r] = pa[p].y;
                As[lcol + 2][r] = pa[p].z; As[lcol + 3][r] = pa[p].w;
                Bs[lcol + 0][r] = pb[p].x; Bs[lcol + 1][r] = pb[p].y;
                Bs[lcol + 2][r] = pb[p].z; Bs[lcol + 3][r] = pb[p].w;
            }
            __syncthreads();
        }
    }

    // epilogue: scalar stores (VOCAB=50257 is odd -> rows not 16B aligned)
#pragma unroll
    for (int i = 0; i < TM; i++) {
        const int m = m0 + ty * TM + i;
        float* crow = C + (size_t)m * VOCAB;
#pragma unroll
        for (int j = 0; j < TN; j++) {
            const int n = n0 + tx * TN + j;
            if (n < VOCAB) crow[n] = acc[i][j];
        }
    }
}

// -----------------------------------------------------------------------------
// Per-row: online log-sum-exp + argmax + target logit -> nll, correct flag
// -----------------------------------------------------------------------------
__global__ void row_stats_kernel(const float* __restrict__ C,
                                 const long long* __restrict__ target)
{
    const int r   = blockIdx.x;
    const int tid = threadIdx.x;
    const float* row = C + (size_t)r * VOCAB;

    float m = -INFINITY, s = 0.f;
    float av = -INFINITY; int ai = VOCAB;

    for (int i = tid; i < VOCAB; i += blockDim.x) {
        const float x = row[i];
        if (x > av || (x == av && i < ai)) { av = x; ai = i; }
        if (x > m) { s = s * expf(m - x) + 1.f; m = x; }
        else       { s += expf(x - m); }
    }

    __shared__ float sm[256], ss[256], sav[256];
    __shared__ int   sai[256];
    sm[tid] = m; ss[tid] = s; sav[tid] = av; sai[tid] = ai;
    __syncthreads();

    for (int off = 128; off > 0; off >>= 1) {
        if (tid < off) {
            const float m2 = sm[tid + off], s2 = ss[tid + off];
            const float M  = fmaxf(sm[tid], m2);
            ss[tid] = ss[tid] * expf(sm[tid] - M) + s2 * expf(m2 - M);
            sm[tid] = M;
            const float av2 = sav[tid + off]; const int ai2 = sai[tid + off];
            if (av2 > sav[tid] || (av2 == sav[tid] && ai2 < sai[tid])) {
                sav[tid] = av2; sai[tid] = ai2;
            }
        }
        __syncthreads();
    }

    if (tid == 0) {
        const int t  = (int)target[r];
        const float xt = row[t];
        g_nll[r]     = (logf(ss[0]) + sm[0]) - xt;
        g_correct[r] = (sai[0] == t) ? 1 : 0;
    }
}

// -----------------------------------------------------------------------------
// Final scalars: loss, token_accuracy, string_accuracy
// -----------------------------------------------------------------------------
__global__ void finalize_kernel(const int* __restrict__ mask,
                                float* __restrict__ out, int n_scalars)
{
    __shared__ float s_lo[256], s_cn[256], s_tk[256];
    __shared__ int   s_seq[BSZ];
    const int tid = threadIdx.x;
    if (tid < BSZ) s_seq[tid] = 1;
    __syncthreads();

    float lo = 0.f, cn = 0.f, tk = 0.f;
    for (int r = tid; r < ROWS; r += 256) {
        const int mk  = mask[r];
        const int cor = g_correct[r];
        if (mk) {
            lo += g_nll[r];
            cn += 1.f;
            tk += (float)cor;
            if (!cor) atomicAnd(&s_seq[r / SEQ], 0);
        }
    }
    s_lo[tid] = lo; s_cn[tid] = cn; s_tk[tid] = tk;
    __syncthreads();

    for (int off = 128; off > 0; off >>= 1) {
        if (tid < off) {
            s_lo[tid] += s_lo[tid + off];
            s_cn[tid] += s_cn[tid + off];
            s_tk[tid] += s_tk[tid + off];
        }
        __syncthreads();
    }

    if (tid == 0) {
        const float nvalid = s_cn[0];
        if (n_scalars >= 1) out[0] = s_lo[0] / nvalid;   // loss
        if (n_scalars >= 2) out[1] = s_tk[0] / nvalid;   // token_accuracy
        if (n_scalars >= 3) {
            float sacc = 0.f;
            for (int b = 0; b < BSZ; b++) sacc += (float)s_seq[b];
            out[2] = sacc / (float)BSZ;                  // string_accuracy
        }
    }
}

// -----------------------------------------------------------------------------
// Entry point. Inputs (metadata order): logits f32, target i64, mask i32, W f32.
// Output layout decided from out_size (defensive: never write OOB):
//   out_size >= 3 + ROWS*VOCAB : [loss, tok_acc, str_acc, tokens...]
//   out_size >= ROWS*VOCAB     : [tokens...] (scalars don't fit -> skip)
//   else                       : scalars only (tokens not representable; still
//                                need them transiently -> reuse nothing, skip)
// -----------------------------------------------------------------------------
extern "C" void kernel_launch(void* const* d_in, const int* in_sizes, int n_in,
                              void* d_out, int out_size)
{
    const float*     logits = (const float*)d_in[0];
    const long long* target = (const long long*)d_in[1];
    const int*       mask   = (const int*)d_in[2];
    const float*     W      = (const float*)d_in[3];

    float* out = (float*)d_out;
    const long long NTOK = (long long)ROWS * VOCAB;

    float* tokens;
    float* scalars;
    int n_scalars;
    if ((long long)out_size >= NTOK + 3) {
        scalars = out; n_scalars = (int)((long long)out_size - NTOK);
        if (n_scalars > 3) n_scalars = 3;
        tokens = out + n_scalars;
    } else if ((long long)out_size >= NTOK) {
        scalars = out; n_scalars = 0;
        tokens  = out;
    } else {
        // No room for the token matrix at all; nothing safe to do for it.
        // (Should not happen given the reference returns evaluate_tokens.)
        return;
    }

    dim3 grid((VOCAB + BN - 1) / BN, ROWS / BM);
    gemm_kernel<<<grid, THREADS>>>(logits, W, tokens);
    row_stats_kernel<<<ROWS, 256>>>(tokens, target);
    if (n_scalars > 0)
        finalize_kernel<<<1, 256>>>(mask, scalars, n_scalars);
}

// round 5
// speedup vs baseline: 2.1726x; 2.1721x over previous
#include <cuda_runtime.h>
#include <cuda_bf16.h>
#include <math.h>
#include <stdint.h>

// ---------------- Problem constants ----------------
#define VOCAB  50257
#define DMODEL 1024
#define SEQ    2048
#define BSZ    2
#define ROWS   (BSZ * SEQ)     // 4096
#define NPAD   50432           // VOCAB padded to multiple of 128

// ---------------- GEMM tiling ----------------
#define BM 128
#define BN 128
#define KC 32                          // k-chunk (bf16 elems) = 64 bytes/row
#define NCHUNK (DMODEL / KC)           // 32
#define ROWB 80                        // smem row stride bytes (64 data + 16 pad)
#define TILE_B (128 * ROWB)            // 10240 per tile
#define STAGE_B (4 * TILE_B)           // Ahi, Alo, Whi, Wlo = 40960
#define NSTAGE 3
#define SMEM_TOTAL (NSTAGE * STAGE_B)  // 122880

// ---------------- Scratch (__device__ globals; no allocs allowed) ----------------
__device__ __nv_bfloat16 g_Ahi[ROWS * DMODEL];
__device__ __nv_bfloat16 g_Alo[ROWS * DMODEL];
__device__ __nv_bfloat16 g_Whi[NPAD * DMODEL];
__device__ __nv_bfloat16 g_Wlo[NPAD * DMODEL];
__device__ float g_nll[ROWS];
__device__ int   g_correct[ROWS];

// ---------------- PTX helpers (all baseline sm_80+ features) ----------------
__device__ __forceinline__ uint32_t smem_u32(const void* p) {
    uint32_t a;
    asm("{ .reg .u64 t; cvta.to.shared.u64 t, %1; cvt.u32.u64 %0, t; }" : "=r"(a) : "l"(p));
    return a;
}
#define CPASYNC16(dst, src) \
    asm volatile("cp.async.cg.shared.global [%0], [%1], 16;\n" :: "r"(dst), "l"(src) : "memory")
#define CPCOMMIT() asm volatile("cp.async.commit_group;\n" ::: "memory")
#define CPWAIT1()  asm volatile("cp.async.wait_group 1;\n" ::: "memory")
#define CPWAIT0()  asm volatile("cp.async.wait_group 0;\n" ::: "memory")

#define LDSM4(r, a) \
    asm volatile("ldmatrix.sync.aligned.m8n8.x4.shared.b16 {%0,%1,%2,%3}, [%4];" \
                 : "=r"((r)[0]), "=r"((r)[1]), "=r"((r)[2]), "=r"((r)[3]) : "r"(a))

#define MMA_BF16(c, a, b) \
    asm volatile("mma.sync.aligned.m16n8k16.row.col.f32.bf16.bf16.f32 " \
                 "{%0,%1,%2,%3}, {%4,%5,%6,%7}, {%8,%9}, {%0,%1,%2,%3};" \
                 : "+f"((c)[0]), "+f"((c)[1]), "+f"((c)[2]), "+f"((c)[3]) \
                 : "r"((a)[0]), "r"((a)[1]), "r"((a)[2]), "r"((a)[3]), \
                   "r"((b)[0]), "r"((b)[1]))

// ---------------- fp32 -> bf16 hi/lo split ----------------
__global__ void convertA_kernel(const float* __restrict__ A) {
    int n = ROWS * DMODEL;
    for (int i = blockIdx.x * blockDim.x + threadIdx.x; i < n; i += gridDim.x * blockDim.x) {
        float x = A[i];
        __nv_bfloat16 h = __float2bfloat16(x);
        g_Ahi[i] = h;
        g_Alo[i] = __float2bfloat16(x - __bfloat162float(h));
    }
}
__global__ void convertW_kernel(const float* __restrict__ W) {
    int n = NPAD * DMODEL;
    for (int i = blockIdx.x * blockDim.x + threadIdx.x; i < n; i += gridDim.x * blockDim.x) {
        int row = i >> 10;
        float x = (row < VOCAB) ? W[i] : 0.f;
        __nv_bfloat16 h = __float2bfloat16(x);
        g_Whi[i] = h;
        g_Wlo[i] = __float2bfloat16(x - __bfloat162float(h));
    }
}

// ---------------- split-bf16 GEMM via mma.sync (HMMA) ----------------
// C[m,n] = sum_k A[m,k] * W[n,k]
// CTA: 128x128 tile; 8 warps (2 m x 4 n); warp tile 64x32; 3-stage cp.async.
__global__ __launch_bounds__(256, 1)
void gemm_mma_kernel(float* __restrict__ C)
{
    extern __shared__ char smem[];
    const uint32_t sb = smem_u32(smem);
    const int tid    = threadIdx.x;
    const int lane   = tid & 31;
    const int wid    = tid >> 5;
    const int warp_m = wid >> 2;       // 0..1  -> 64 rows
    const int warp_n = wid & 3;        // 0..3  -> 32 cols
    const int m0     = blockIdx.x * BM;  // m fastest => W tile L2 reuse
    const int n0     = blockIdx.y * BN;

    const char* pAh = (const char*)g_Ahi + (size_t)m0 * (DMODEL * 2);
    const char* pAl = (const char*)g_Alo + (size_t)m0 * (DMODEL * 2);
    const char* pWh = (const char*)g_Whi + (size_t)n0 * (DMODEL * 2);
    const char* pWl = (const char*)g_Wlo + (size_t)n0 * (DMODEL * 2);

    // ---- stage loader: 2048 x 16B cp.async, 8 per thread, no divergence ----
    auto load_chunk = [&](int s, int k) {
        const uint32_t base = sb + s * STAGE_B;
        const size_t koff = (size_t)k * (KC * 2);      // 64 bytes
#pragma unroll
        for (int q = 0; q < 8; q++) {
            int i    = tid + q * 256;
            int tile = i >> 9;                // 0:Ahi 1:Alo 2:Whi 3:Wlo
            int j    = i & 511;
            int row  = j >> 2;
            int c16  = (j & 3) << 4;
            uint32_t dst = base + tile * TILE_B + row * ROWB + c16;
            const char* src;
            if      (tile == 0) src = pAh;
            else if (tile == 1) src = pAl;
            else if (tile == 2) src = pWh;
            else                src = pWl;
            CPASYNC16(dst, src + (size_t)row * 2048 + koff + c16);
        }
        CPCOMMIT();
    };

    float acc[4][4][4];                       // [m-tile][n-tile][frag]
#pragma unroll
    for (int i = 0; i < 4; i++)
#pragma unroll
        for (int j = 0; j < 4; j++)
#pragma unroll
            for (int e = 0; e < 4; e++) acc[i][j][e] = 0.f;

    load_chunk(0, 0);
    load_chunk(1, 1);

    // precomputed in-tile ldmatrix lane offsets
    const uint32_t aLaneOff = (uint32_t)(lane & 15) * ROWB + (uint32_t)(lane >> 4) * 16;
    const uint32_t bLaneOff = ((uint32_t)((lane >> 4) << 3) + (lane & 7)) * ROWB +
                              (uint32_t)((lane >> 3) & 1) * 16;

    for (int k = 0; k < NCHUNK; k++) {
        const int s = k % NSTAGE;
        if (k < NCHUNK - 1) CPWAIT1(); else CPWAIT0();
        __syncthreads();

        if (k + 2 < NCHUNK) load_chunk((k + 2) % NSTAGE, k + 2);

        const uint32_t base = sb + s * STAGE_B;
        const uint32_t aHi = base + (warp_m * 64) * ROWB + aLaneOff;
        const uint32_t aLo = aHi + TILE_B;
        const uint32_t bHi = base + 2 * TILE_B + (warp_n * 32) * ROWB + bLaneOff;
        const uint32_t bLo = bHi + TILE_B;

#pragma unroll
        for (int ks = 0; ks < 2; ks++) {
            const uint32_t kb = ks * 32;
            uint32_t ah[4][4], al[4][4], bh[4][2], bl[4][2];
#pragma unroll
            for (int ti = 0; ti < 4; ti++) {
                LDSM4(ah[ti], aHi + ti * (16 * ROWB) + kb);
                LDSM4(al[ti], aLo + ti * (16 * ROWB) + kb);
            }
#pragma unroll
            for (int nb = 0; nb < 2; nb++) {
                uint32_t r[4];
                LDSM4(r, bHi + nb * (16 * ROWB) + kb);
                bh[2 * nb][0] = r[0]; bh[2 * nb][1] = r[1];
                bh[2 * nb + 1][0] = r[2]; bh[2 * nb + 1][1] = r[3];
                LDSM4(r, bLo + nb * (16 * ROWB) + kb);
                bl[2 * nb][0] = r[0]; bl[2 * nb][1] = r[1];
                bl[2 * nb + 1][0] = r[2]; bl[2 * nb + 1][1] = r[3];
            }
#pragma unroll
            for (int ti = 0; ti < 4; ti++)
#pragma unroll
                for (int ni = 0; ni < 4; ni++) {
                    MMA_BF16(acc[ti][ni], ah[ti], bh[ni]);   // hi*hi
                    MMA_BF16(acc[ti][ni], ah[ti], bl[ni]);   // hi*lo
                    MMA_BF16(acc[ti][ni], al[ti], bh[ni]);   // lo*hi
                }
        }
        __syncthreads();   // all warps done with stage s before it is reloaded
    }

    // ---- epilogue: regs -> gmem ----
    const int mrow = m0 + warp_m * 64 + (lane >> 2);
    const int ncol = n0 + warp_n * 32 + 2 * (lane & 3);
#pragma unroll
    for (int ti = 0; ti < 4; ti++) {
#pragma unroll
        for (int half = 0; half < 2; half++) {
            const int r = mrow + ti * 16 + half * 8;
            float* crow = C + (size_t)r * VOCAB;
#pragma unroll
            for (int ni = 0; ni < 4; ni++) {
                const int c = ncol + ni * 8;
                if (c < VOCAB)     crow[c]     = acc[ti][ni][half * 2];
                if (c + 1 < VOCAB) crow[c + 1] = acc[ti][ni][half * 2 + 1];
            }
        }
    }
}

// ---------------- per-row logsumexp + argmax ----------------
__global__ void row_stats_kernel(const float* __restrict__ C,
                                 const long long* __restrict__ target)
{
    const int r   = blockIdx.x;
    const int tid = threadIdx.x;
    const float* row = C + (size_t)r * VOCAB;

    float m = -INFINITY, s = 0.f;
    float av = -INFINITY; int ai = VOCAB;

    for (int i = tid; i < VOCAB; i += blockDim.x) {
        const float x = row[i];
        if (x > av || (x == av && i < ai)) { av = x; ai = i; }
        if (x > m) { s = s * expf(m - x) + 1.f; m = x; }
        else       { s += expf(x - m); }
    }

    __shared__ float sm[256], ss[256], sav[256];
    __shared__ int   sai[256];
    sm[tid] = m; ss[tid] = s; sav[tid] = av; sai[tid] = ai;
    __syncthreads();

    for (int off = 128; off > 0; off >>= 1) {
        if (tid < off) {
            const float m2 = sm[tid + off], s2 = ss[tid + off];
            const float M  = fmaxf(sm[tid], m2);
            ss[tid] = ss[tid] * expf(sm[tid] - M) + s2 * expf(m2 - M);
            sm[tid] = M;
            const float av2 = sav[tid + off]; const int ai2 = sai[tid + off];
            if (av2 > sav[tid] || (av2 == sav[tid] && ai2 < sai[tid])) {
                sav[tid] = av2; sai[tid] = ai2;
            }
        }
        __syncthreads();
    }

    if (tid == 0) {
        const int t  = (int)target[r];
        const float xt = row[t];
        g_nll[r]     = (logf(ss[0]) + sm[0]) - xt;
        g_correct[r] = (sai[0] == t) ? 1 : 0;
    }
}

// ---------------- final scalars ----------------
__global__ void finalize_kernel(const int* __restrict__ mask,
                                float* __restrict__ out, int n_scalars)
{
    __shared__ float s_lo[256], s_cn[256], s_tk[256];
    __shared__ int   s_seq[BSZ];
    const int tid = threadIdx.x;
    if (tid < BSZ) s_seq[tid] = 1;
    __syncthreads();

    float lo = 0.f, cn = 0.f, tk = 0.f;
    for (int r = tid; r < ROWS; r += 256) {
        const int mk  = mask[r];
        const int cor = g_correct[r];
        if (mk) {
            lo += g_nll[r];
            cn += 1.f;
            tk += (float)cor;
            if (!cor) atomicAnd(&s_seq[r / SEQ], 0);
        }
    }
    s_lo[tid] = lo; s_cn[tid] = cn; s_tk[tid] = tk;
    __syncthreads();

    for (int off = 128; off > 0; off >>= 1) {
        if (tid < off) {
            s_lo[tid] += s_lo[tid + off];
            s_cn[tid] += s_cn[tid + off];
            s_tk[tid] += s_tk[tid + off];
        }
        __syncthreads();
    }

    if (tid == 0) {
        const float nvalid = s_cn[0];
        if (n_scalars >= 1) out[0] = s_lo[0] / nvalid;
        if (n_scalars >= 2) out[1] = s_tk[0] / nvalid;
        if (n_scalars >= 3) {
            float sacc = 0.f;
            for (int b = 0; b < BSZ; b++) sacc += (float)s_seq[b];
            out[2] = sacc / (float)BSZ;
        }
    }
}

// ---------------- entry ----------------
extern "C" void kernel_launch(void* const* d_in, const int* in_sizes, int n_in,
                              void* d_out, int out_size)
{
    const float*     logits = (const float*)d_in[0];
    const long long* target = (const long long*)d_in[1];
    const int*       mask   = (const int*)d_in[2];
    const float*     W      = (const float*)d_in[3];

    float* out = (float*)d_out;
    const long long NTOK = (long long)ROWS * VOCAB;

    float* tokens;
    float* scalars;
    int n_scalars;
    if ((long long)out_size >= NTOK + 3) {
        scalars = out;
        n_scalars = (int)((long long)out_size - NTOK);
        if (n_scalars > 3) n_scalars = 3;
        tokens = out + n_scalars;
    } else if ((long long)out_size >= NTOK) {
        scalars = out; n_scalars = 0; tokens = out;
    } else {
        return;
    }

    cudaFuncSetAttribute(gemm_mma_kernel,
                         cudaFuncAttributeMaxDynamicSharedMemorySize, SMEM_TOTAL);

    convertA_kernel<<<2048, 256>>>(logits);
    convertW_kernel<<<16384, 256>>>(W);

    dim3 grid(ROWS / BM, NPAD / BN);   // (32, 394), m fastest
    gemm_mma_kernel<<<grid, 256, SMEM_TOTAL>>>(tokens);

    row_stats_kernel<<<ROWS, 256>>>(tokens, target);
    if (n_scalars > 0)
        finalize_kernel<<<1, 256>>>(mask, scalars, n_scalars);
}

// round 6
// speedup vs baseline: 2.1735x; 1.0004x over previous
#include <cuda_runtime.h>
#include <cuda_bf16.h>
#include <math.h>
#include <stdint.h>

// ---------------- Problem constants ----------------
#define VOCAB  50257
#define DMODEL 1024
#define SEQ    2048
#define BSZ    2
#define ROWS   (BSZ * SEQ)     // 4096
#define NPAD   50432           // VOCAB padded to multiple of 128

// ---------------- GEMM tiling ----------------
#define BM 128
#define BN 128
#define KC 32                          // k-chunk (bf16 elems) = 64 bytes/row
#define NCHUNK (DMODEL / KC)           // 32
#define ROWB 80                        // smem row stride bytes (64 data + 16 pad)
#define TILE_B (128 * ROWB)            // 10240 per tile
#define STAGE_B (4 * TILE_B)           // Ahi, Alo, Whi, Wlo = 40960
#define NSTAGE 3
#define SMEM_TOTAL (NSTAGE * STAGE_B)  // 122880

// ---------------- Scratch (__device__ globals; no allocs allowed) ----------------
__device__ __nv_bfloat16 g_Ahi[ROWS * DMODEL];
__device__ __nv_bfloat16 g_Alo[ROWS * DMODEL];
__device__ __nv_bfloat16 g_Whi[NPAD * DMODEL];
__device__ __nv_bfloat16 g_Wlo[NPAD * DMODEL];
__device__ float g_nll[ROWS];
__device__ int   g_correct[ROWS];

// ---------------- PTX helpers (all baseline sm_80+ features) ----------------
__device__ __forceinline__ uint32_t smem_u32(const void* p) {
    uint32_t a;
    asm("{ .reg .u64 t; cvta.to.shared.u64 t, %1; cvt.u32.u64 %0, t; }" : "=r"(a) : "l"(p));
    return a;
}
#define CPASYNC16(dst, src) \
    asm volatile("cp.async.cg.shared.global [%0], [%1], 16;\n" :: "r"(dst), "l"(src) : "memory")
#define CPCOMMIT() asm volatile("cp.async.commit_group;\n" ::: "memory")
#define CPWAIT1()  asm volatile("cp.async.wait_group 1;\n" ::: "memory")
#define CPWAIT0()  asm volatile("cp.async.wait_group 0;\n" ::: "memory")

#define LDSM4(r, a) \
    asm volatile("ldmatrix.sync.aligned.m8n8.x4.shared.b16 {%0,%1,%2,%3}, [%4];" \
                 : "=r"((r)[0]), "=r"((r)[1]), "=r"((r)[2]), "=r"((r)[3]) : "r"(a))

#define MMA_BF16(c, a, b) \
    asm volatile("mma.sync.aligned.m16n8k16.row.col.f32.bf16.bf16.f32 " \
                 "{%0,%1,%2,%3}, {%4,%5,%6,%7}, {%8,%9}, {%0,%1,%2,%3};" \
                 : "+f"((c)[0]), "+f"((c)[1]), "+f"((c)[2]), "+f"((c)[3]) \
                 : "r"((a)[0]), "r"((a)[1]), "r"((a)[2]), "r"((a)[3]), \
                   "r"((b)[0]), "r"((b)[1]))

// ---------------- fp32 -> bf16 hi/lo split ----------------
__global__ void convertA_kernel(const float* __restrict__ A) {
    int n = ROWS * DMODEL;
    for (int i = blockIdx.x * blockDim.x + threadIdx.x; i < n; i += gridDim.x * blockDim.x) {
        float x = A[i];
        __nv_bfloat16 h = __float2bfloat16(x);
        g_Ahi[i] = h;
        g_Alo[i] = __float2bfloat16(x - __bfloat162float(h));
    }
}
__global__ void convertW_kernel(const float* __restrict__ W) {
    int n = NPAD * DMODEL;
    for (int i = blockIdx.x * blockDim.x + threadIdx.x; i < n; i += gridDim.x * blockDim.x) {
        int row = i >> 10;
        float x = (row < VOCAB) ? W[i] : 0.f;
        __nv_bfloat16 h = __float2bfloat16(x);
        g_Whi[i] = h;
        g_Wlo[i] = __float2bfloat16(x - __bfloat162float(h));
    }
}

// ---------------- split-bf16 GEMM via mma.sync (HMMA) ----------------
// C[m,n] = sum_k A[m,k] * W[n,k]
// CTA: 128x128 tile; 8 warps (2 m x 4 n); warp tile 64x32; 3-stage cp.async.
__global__ __launch_bounds__(256, 1)
void gemm_mma_kernel(float* __restrict__ C)
{
    extern __shared__ char smem[];
    const uint32_t sb = smem_u32(smem);
    const int tid    = threadIdx.x;
    const int lane   = tid & 31;
    const int wid    = tid >> 5;
    const int warp_m = wid >> 2;       // 0..1  -> 64 rows
    const int warp_n = wid & 3;        // 0..3  -> 32 cols
    const int m0     = blockIdx.x * BM;  // m fastest => W tile L2 reuse
    const int n0     = blockIdx.y * BN;

    const char* pAh = (const char*)g_Ahi + (size_t)m0 * (DMODEL * 2);
    const char* pAl = (const char*)g_Alo + (size_t)m0 * (DMODEL * 2);
    const char* pWh = (const char*)g_Whi + (size_t)n0 * (DMODEL * 2);
    const char* pWl = (const char*)g_Wlo + (size_t)n0 * (DMODEL * 2);

    // ---- stage loader: 2048 x 16B cp.async, 8 per thread, no divergence ----
    auto load_chunk = [&](int s, int k) {
        const uint32_t base = sb + s * STAGE_B;
        const size_t koff = (size_t)k * (KC * 2);      // 64 bytes
#pragma unroll
        for (int q = 0; q < 8; q++) {
            int i    = tid + q * 256;
            int tile = i >> 9;                // 0:Ahi 1:Alo 2:Whi 3:Wlo
            int j    = i & 511;
            int row  = j >> 2;
            int c16  = (j & 3) << 4;
            uint32_t dst = base + tile * TILE_B + row * ROWB + c16;
            const char* src;
            if      (tile == 0) src = pAh;
            else if (tile == 1) src = pAl;
            else if (tile == 2) src = pWh;
            else                src = pWl;
            CPASYNC16(dst, src + (size_t)row * 2048 + koff + c16);
        }
        CPCOMMIT();
    };

    float acc[4][4][4];                       // [m-tile][n-tile][frag]
#pragma unroll
    for (int i = 0; i < 4; i++)
#pragma unroll
        for (int j = 0; j < 4; j++)
#pragma unroll
            for (int e = 0; e < 4; e++) acc[i][j][e] = 0.f;

    load_chunk(0, 0);
    load_chunk(1, 1);

    // precomputed in-tile ldmatrix lane offsets
    const uint32_t aLaneOff = (uint32_t)(lane & 15) * ROWB + (uint32_t)(lane >> 4) * 16;
    const uint32_t bLaneOff = ((uint32_t)((lane >> 4) << 3) + (lane & 7)) * ROWB +
                              (uint32_t)((lane >> 3) & 1) * 16;

    for (int k = 0; k < NCHUNK; k++) {
        const int s = k % NSTAGE;
        if (k < NCHUNK - 1) CPWAIT1(); else CPWAIT0();
        __syncthreads();

        if (k + 2 < NCHUNK) load_chunk((k + 2) % NSTAGE, k + 2);

        const uint32_t base = sb + s * STAGE_B;
        const uint32_t aHi = base + (warp_m * 64) * ROWB + aLaneOff;
        const uint32_t aLo = aHi + TILE_B;
        const uint32_t bHi = base + 2 * TILE_B + (warp_n * 32) * ROWB + bLaneOff;
        const uint32_t bLo = bHi + TILE_B;

#pragma unroll
        for (int ks = 0; ks < 2; ks++) {
            const uint32_t kb = ks * 32;
            uint32_t ah[4][4], al[4][4], bh[4][2], bl[4][2];
#pragma unroll
            for (int ti = 0; ti < 4; ti++) {
                LDSM4(ah[ti], aHi + ti * (16 * ROWB) + kb);
                LDSM4(al[ti], aLo + ti * (16 * ROWB) + kb);
            }
#pragma unroll
            for (int nb = 0; nb < 2; nb++) {
                uint32_t r[4];
                LDSM4(r, bHi + nb * (16 * ROWB) + kb);
                bh[2 * nb][0] = r[0]; bh[2 * nb][1] = r[1];
                bh[2 * nb + 1][0] = r[2]; bh[2 * nb + 1][1] = r[3];
                LDSM4(r, bLo + nb * (16 * ROWB) + kb);
                bl[2 * nb][0] = r[0]; bl[2 * nb][1] = r[1];
                bl[2 * nb + 1][0] = r[2]; bl[2 * nb + 1][1] = r[3];
            }
#pragma unroll
            for (int ti = 0; ti < 4; ti++)
#pragma unroll
                for (int ni = 0; ni < 4; ni++) {
                    MMA_BF16(acc[ti][ni], ah[ti], bh[ni]);   // hi*hi
                    MMA_BF16(acc[ti][ni], ah[ti], bl[ni]);   // hi*lo
                    MMA_BF16(acc[ti][ni], al[ti], bh[ni]);   // lo*hi
                }
        }
        __syncthreads();   // all warps done with stage s before it is reloaded
    }

    // ---- epilogue: regs -> gmem ----
    const int mrow = m0 + warp_m * 64 + (lane >> 2);
    const int ncol = n0 + warp_n * 32 + 2 * (lane & 3);
#pragma unroll
    for (int ti = 0; ti < 4; ti++) {
#pragma unroll
        for (int half = 0; half < 2; half++) {
            const int r = mrow + ti * 16 + half * 8;
            float* crow = C + (size_t)r * VOCAB;
#pragma unroll
            for (int ni = 0; ni < 4; ni++) {
                const int c = ncol + ni * 8;
                if (c < VOCAB)     crow[c]     = acc[ti][ni][half * 2];
                if (c + 1 < VOCAB) crow[c + 1] = acc[ti][ni][half * 2 + 1];
            }
        }
    }
}

// ---------------- per-row logsumexp + argmax ----------------
__global__ void row_stats_kernel(const float* __restrict__ C,
                                 const long long* __restrict__ target)
{
    const int r   = blockIdx.x;
    const int tid = threadIdx.x;
    const float* row = C + (size_t)r * VOCAB;

    float m = -INFINITY, s = 0.f;
    float av = -INFINITY; int ai = VOCAB;

    for (int i = tid; i < VOCAB; i += blockDim.x) {
        const float x = row[i];
        if (x > av || (x == av && i < ai)) { av = x; ai = i; }
        if (x > m) { s = s * expf(m - x) + 1.f; m = x; }
        else       { s += expf(x - m); }
    }

    __shared__ float sm[256], ss[256], sav[256];
    __shared__ int   sai[256];
    sm[tid] = m; ss[tid] = s; sav[tid] = av; sai[tid] = ai;
    __syncthreads();

    for (int off = 128; off > 0; off >>= 1) {
        if (tid < off) {
            const float m2 = sm[tid + off], s2 = ss[tid + off];
            const float M  = fmaxf(sm[tid], m2);
            ss[tid] = ss[tid] * expf(sm[tid] - M) + s2 * expf(m2 - M);
            sm[tid] = M;
            const float av2 = sav[tid + off]; const int ai2 = sai[tid + off];
            if (av2 > sav[tid] || (av2 == sav[tid] && ai2 < sai[tid])) {
                sav[tid] = av2; sai[tid] = ai2;
            }
        }
        __syncthreads();
    }

    if (tid == 0) {
        const int t  = (int)target[r];
        const float xt = row[t];
        g_nll[r]     = (logf(ss[0]) + sm[0]) - xt;
        g_correct[r] = (sai[0] == t) ? 1 : 0;
    }
}

// ---------------- final scalars ----------------
__global__ void finalize_kernel(const int* __restrict__ mask,
                                float* __restrict__ out, int n_scalars)
{
    __shared__ float s_lo[256], s_cn[256], s_tk[256];
    __shared__ int   s_seq[BSZ];
    const int tid = threadIdx.x;
    if (tid < BSZ) s_seq[tid] = 1;
    __syncthreads();

    float lo = 0.f, cn = 0.f, tk = 0.f;
    for (int r = tid; r < ROWS; r += 256) {
        const int mk  = mask[r];
        const int cor = g_correct[r];
        if (mk) {
            lo += g_nll[r];
            cn += 1.f;
            tk += (float)cor;
            if (!cor) atomicAnd(&s_seq[r / SEQ], 0);
        }
    }
    s_lo[tid] = lo; s_cn[tid] = cn; s_tk[tid] = tk;
    __syncthreads();

    for (int off = 128; off > 0; off >>= 1) {
        if (tid < off) {
            s_lo[tid] += s_lo[tid + off];
            s_cn[tid] += s_cn[tid + off];
            s_tk[tid] += s_tk[tid + off];
        }
        __syncthreads();
    }

    if (tid == 0) {
        const float nvalid = s_cn[0];
        if (n_scalars >= 1) out[0] = s_lo[0] / nvalid;
        if (n_scalars >= 2) out[1] = s_tk[0] / nvalid;
        if (n_scalars >= 3) {
            float sacc = 0.f;
            for (int b = 0; b < BSZ; b++) sacc += (float)s_seq[b];
            out[2] = sacc / (float)BSZ;
        }
    }
}

// ---------------- entry ----------------
extern "C" void kernel_launch(void* const* d_in, const int* in_sizes, int n_in,
                              void* d_out, int out_size)
{
    const float*     logits = (const float*)d_in[0];
    const long long* target = (const long long*)d_in[1];
    const int*       mask   = (const int*)d_in[2];
    const float*     W      = (const float*)d_in[3];

    float* out = (float*)d_out;
    const long long NTOK = (long long)ROWS * VOCAB;

    float* tokens;
    float* scalars;
    int n_scalars;
    if ((long long)out_size >= NTOK + 3) {
        scalars = out;
        n_scalars = (int)((long long)out_size - NTOK);
        if (n_scalars > 3) n_scalars = 3;
        tokens = out + n_scalars;
    } else if ((long long)out_size >= NTOK) {
        scalars = out; n_scalars = 0; tokens = out;
    } else {
        return;
    }

    cudaFuncSetAttribute(gemm_mma_kernel,
                         cudaFuncAttributeMaxDynamicSharedMemorySize, SMEM_TOTAL);

    convertA_kernel<<<2048, 256>>>(logits);
    convertW_kernel<<<16384, 256>>>(W);

    dim3 grid(ROWS / BM, NPAD / BN);   // (32, 394), m fastest
    gemm_mma_kernel<<<grid, 256, SMEM_TOTAL>>>(tokens);

    row_stats_kernel<<<ROWS, 256>>>(tokens, target);
    if (n_scalars > 0)
        finalize_kernel<<<1, 256>>>(mask, scalars, n_scalars);
}

// round 9
// speedup vs baseline: 2.4713x; 1.1370x over previous
#include <cuda_runtime.h>
#include <cuda_bf16.h>
#include <math.h>
#include <stdint.h>

// ---------------- Problem constants ----------------
#define VOCAB  50257
#define DMODEL 1024
#define SEQ    2048
#define BSZ    2
#define ROWS   (BSZ * SEQ)     // 4096
#define NPAD   50432           // VOCAB padded to multiple of 256 (197*256)

// ---------------- GEMM tiling ----------------
#define BM 128
#define BN 256
#define KC 32                          // k-chunk (bf16 elems) = 64 bytes/row
#define NCHUNK (DMODEL / KC)           // 32
#define ROWB 80                        // smem row stride bytes (64 data + 16 pad)
#define TILE_A (128 * ROWB)            // 10240
#define TILE_W (256 * ROWB)            // 20480
#define STAGE_B (2 * TILE_A + 2 * TILE_W)   // 61440
#define NSTAGE 3
#define SMEM_TOTAL (NSTAGE * STAGE_B)  // 184320

// ---------------- Scratch (__device__ globals; no allocs allowed) ----------------
__device__ __nv_bfloat16 g_Ahi[ROWS * DMODEL];
__device__ __nv_bfloat16 g_Alo[ROWS * DMODEL];
__device__ __nv_bfloat16 g_Whi[NPAD * DMODEL];
__device__ __nv_bfloat16 g_Wlo[NPAD * DMODEL];
__device__ float g_nll[ROWS];
__device__ int   g_correct[ROWS];

// ---------------- PTX helpers (baseline sm_80+ features only) ----------------
__device__ __forceinline__ uint32_t smem_u32(const void* p) {
    uint32_t a;
    asm("{ .reg .u64 t; cvta.to.shared.u64 t, %1; cvt.u32.u64 %0, t; }" : "=r"(a) : "l"(p));
    return a;
}
#define CPASYNC16(dst, src) \
    asm volatile("cp.async.cg.shared.global [%0], [%1], 16;\n" :: "r"(dst), "l"(src) : "memory")
#define CPCOMMIT() asm volatile("cp.async.commit_group;\n" ::: "memory")
#define CPWAIT1()  asm volatile("cp.async.wait_group 1;\n" ::: "memory")
#define CPWAIT0()  asm volatile("cp.async.wait_group 0;\n" ::: "memory")

#define LDSM4(r, a) \
    asm volatile("ldmatrix.sync.aligned.m8n8.x4.shared.b16 {%0,%1,%2,%3}, [%4];" \
                 : "=r"((r)[0]), "=r"((r)[1]), "=r"((r)[2]), "=r"((r)[3]) : "r"(a))

#define MMA_BF16(c, a, b) \
    asm volatile("mma.sync.aligned.m16n8k16.row.col.f32.bf16.bf16.f32 " \
                 "{%0,%1,%2,%3}, {%4,%5,%6,%7}, {%8,%9}, {%0,%1,%2,%3};" \
                 : "+f"((c)[0]), "+f"((c)[1]), "+f"((c)[2]), "+f"((c)[3]) \
                 : "r"((a)[0]), "r"((a)[1]), "r"((a)[2]), "r"((a)[3]), \
                   "r"((b)[0]), "r"((b)[1]))

// ---------------- fp32 -> bf16 hi/lo split ----------------
__global__ void convertA_kernel(const float* __restrict__ A) {
    int n = ROWS * DMODEL;
    for (int i = blockIdx.x * blockDim.x + threadIdx.x; i < n; i += gridDim.x * blockDim.x) {
        float x = A[i];
        __nv_bfloat16 h = __float2bfloat16(x);
        g_Ahi[i] = h;
        g_Alo[i] = __float2bfloat16(x - __bfloat162float(h));
    }
}
__global__ void convertW_kernel(const float* __restrict__ W) {
    int n = NPAD * DMODEL;
    for (int i = blockIdx.x * blockDim.x + threadIdx.x; i < n; i += gridDim.x * blockDim.x) {
        int row = i >> 10;
        float x = (row < VOCAB) ? W[i] : 0.f;
        __nv_bfloat16 h = __float2bfloat16(x);
        g_Whi[i] = h;
        g_Wlo[i] = __float2bfloat16(x - __bfloat162float(h));
    }
}

// ---------------- split-bf16 GEMM via mma.sync (HMMA) ----------------
// C[m,n] = sum_k A[m,k] * W[n,k]
// CTA: 128x256; 8 warps (2 m x 4 n); warp tile 64x64; 3-stage cp.async pipeline.
__global__ __launch_bounds__(256, 1)
void gemm_mma_kernel(float* __restrict__ C)
{
    extern __shared__ char smem[];
    const uint32_t sb = smem_u32(smem);
    const int tid    = threadIdx.x;
    const int lane   = tid & 31;
    const int wid    = tid >> 5;
    const int warp_m = wid >> 2;         // 0..1 -> 64 rows
    const int warp_n = wid & 3;          // 0..3 -> 64 cols
    const int m0     = blockIdx.x * BM;  // m fastest => W tile L2 reuse
    const int n0     = blockIdx.y * BN;

    const char* pAh = (const char*)g_Ahi + (size_t)m0 * (DMODEL * 2);
    const char* pAl = (const char*)g_Alo + (size_t)m0 * (DMODEL * 2);
    const char* pWh = (const char*)g_Whi + (size_t)n0 * (DMODEL * 2);
    const char* pWl = (const char*)g_Wlo + (size_t)n0 * (DMODEL * 2);

    // ---- stage loader: 3072 x 16B cp.async, 12 per thread.
    // i = tid + q*256 -> region is uniform per q:
    //   q 0-1: Ahi, q 2-3: Alo, q 4-7: Whi, q 8-11: Wlo
    auto load_chunk = [&](int s, int k) {
        const uint32_t base = sb + s * STAGE_B;
        const size_t koff = (size_t)k * (KC * 2);      // 64 bytes
#pragma unroll
        for (int q = 0; q < 12; q++) {
            const int i = tid + q * 256;
            const char* src;
            uint32_t dstBase;
            int j;
            if (i < 512)        { src = pAh; dstBase = base;                      j = i; }
            else if (i < 1024)  { src = pAl; dstBase = base + TILE_A;             j = i - 512; }
            else if (i < 2048)  { src = pWh; dstBase = base + 2 * TILE_A;         j = i - 1024; }
            else                { src = pWl; dstBase = base + 2 * TILE_A + TILE_W; j = i - 2048; }
            const int row = j >> 2;
            const int c16 = (j & 3) << 4;
            CPASYNC16(dstBase + row * ROWB + c16,
                      src + (size_t)row * 2048 + koff + c16);
        }
        CPCOMMIT();
    };

    float acc[4][8][4];                       // [m-tile][n-tile][frag]
#pragma unroll
    for (int i = 0; i < 4; i++)
#pragma unroll
        for (int j = 0; j < 8; j++)
#pragma unroll
            for (int e = 0; e < 4; e++) acc[i][j][e] = 0.f;

    load_chunk(0, 0);
    load_chunk(1, 1);

    // in-tile ldmatrix lane offsets (mapping validated in R6)
    const uint32_t aLaneOff = (uint32_t)(lane & 15) * ROWB + (uint32_t)(lane >> 4) * 16;
    const uint32_t bLaneOff = ((uint32_t)((lane >> 4) << 3) + (lane & 7)) * ROWB +
                              (uint32_t)((lane >> 3) & 1) * 16;

    for (int k = 0; k < NCHUNK; k++) {
        const int s = k % NSTAGE;
        if (k < NCHUNK - 1) CPWAIT1(); else CPWAIT0();
        __syncthreads();

        if (k + 2 < NCHUNK) load_chunk((k + 2) % NSTAGE, k + 2);

        const uint32_t base = sb + s * STAGE_B;
        const uint32_t aHi = base + (warp_m * 64) * ROWB + aLaneOff;
        const uint32_t aLo = aHi + TILE_A;
        const uint32_t bHi = base + 2 * TILE_A + (warp_n * 64) * ROWB + bLaneOff;
        const uint32_t bLo = bHi + TILE_W;

#pragma unroll
        for (int ks = 0; ks < 2; ks++) {
            const uint32_t kb = ks * 32;
            uint32_t ah[4][4], al[4][4], bh[8][2], bl[8][2];
#pragma unroll
            for (int ti = 0; ti < 4; ti++) {
                LDSM4(ah[ti], aHi + ti * (16 * ROWB) + kb);
                LDSM4(al[ti], aLo + ti * (16 * ROWB) + kb);
            }
#pragma unroll
            for (int nb = 0; nb < 4; nb++) {
                uint32_t r[4];
                LDSM4(r, bHi + nb * (16 * ROWB) + kb);
                bh[2 * nb][0] = r[0]; bh[2 * nb][1] = r[1];
                bh[2 * nb + 1][0] = r[2]; bh[2 * nb + 1][1] = r[3];
                LDSM4(r, bLo + nb * (16 * ROWB) + kb);
                bl[2 * nb][0] = r[0]; bl[2 * nb][1] = r[1];
                bl[2 * nb + 1][0] = r[2]; bl[2 * nb + 1][1] = r[3];
            }
#pragma unroll
            for (int ti = 0; ti < 4; ti++)
#pragma unroll
                for (int ni = 0; ni < 8; ni++) {
                    MMA_BF16(acc[ti][ni], ah[ti], bh[ni]);   // hi*hi
                    MMA_BF16(acc[ti][ni], ah[ti], bl[ni]);   // hi*lo
                    MMA_BF16(acc[ti][ni], al[ti], bh[ni]);   // lo*hi
                }
        }
        __syncthreads();   // all warps done with stage s before it is reloaded
    }

    // ---- epilogue: regs -> gmem ----
    const int mrow = m0 + warp_m * 64 + (lane >> 2);
    const int ncol = n0 + warp_n * 64 + 2 * (lane & 3);
#pragma unroll
    for (int ti = 0; ti < 4; ti++) {
#pragma unroll
        for (int half = 0; half < 2; half++) {
            const int r = mrow + ti * 16 + half * 8;
            float* crow = C + (size_t)r * VOCAB;
#pragma unroll
            for (int ni = 0; ni < 8; ni++) {
                const int c = ncol + ni * 8;
                if (c < VOCAB)     crow[c]     = acc[ti][ni][half * 2];
                if (c + 1 < VOCAB) crow[c + 1] = acc[ti][ni][half * 2 + 1];
            }
        }
    }
}

// ---------------- per-row max/argmax + sum-exp (two-pass) ----------------
__global__ void row_stats_kernel(const float* __restrict__ C,
                                 const long long* __restrict__ target)
{
    const int r   = blockIdx.x;
    const int tid = threadIdx.x;
    const float* row = C + (size_t)r * VOCAB;

    // FIX(R7): derive float4 alignment from the ACTUAL pointer (C itself sits
    // at +3 floats inside d_out), not from r*VOCAB alone.
    const int lead  = (int)((4 - (((uintptr_t)row >> 2) & 3)) & 3);
    const int n4    = (VOCAB - lead) >> 2;
    const int tail0 = lead + n4 * 4;
    const float4* row4 = (const float4*)(row + lead);

    // ---- pass 1: max + argmax ----
    float av = -INFINITY; int ai = 0;
    if (tid < lead) { float x = row[tid]; if (x > av) { av = x; ai = tid; } }
    for (int j = tid; j < n4; j += 256) {
        const float4 v = row4[j];
        const int i = lead + 4 * j;
        if (v.x > av) { av = v.x; ai = i; }
        if (v.y > av) { av = v.y; ai = i + 1; }
        if (v.z > av) { av = v.z; ai = i + 2; }
        if (v.w > av) { av = v.w; ai = i + 3; }
    }
    for (int i = tail0 + tid; i < VOCAB; i += 256) {
        const float x = row[i];
        if (x > av) { av = x; ai = i; }
    }

    __shared__ float sav[256];
    __shared__ int   sai[256];
    __shared__ float ss[256];
    sav[tid] = av; sai[tid] = ai;
    __syncthreads();
    for (int off = 128; off > 0; off >>= 1) {
        if (tid < off) {
            const float a2 = sav[tid + off]; const int i2 = sai[tid + off];
            if (a2 > sav[tid] || (a2 == sav[tid] && i2 < sai[tid])) {
                sav[tid] = a2; sai[tid] = i2;
            }
        }
        __syncthreads();
    }
    const float m = sav[0];

    // ---- pass 2: sum exp(x - m) (re-read; mostly L2 hits) ----
    float s = 0.f;
    if (tid < lead) s += __expf(row[tid] - m);
    for (int j = tid; j < n4; j += 256) {
        const float4 v = row4[j];
        s += __expf(v.x - m) + __expf(v.y - m) + __expf(v.z - m) + __expf(v.w - m);
    }
    for (int i = tail0 + tid; i < VOCAB; i += 256) s += __expf(row[i] - m);

    ss[tid] = s;
    __syncthreads();
    for (int off = 128; off > 0; off >>= 1) {
        if (tid < off) ss[tid] += ss[tid + off];
        __syncthreads();
    }

    if (tid == 0) {
        const int t = (int)target[r];
        g_nll[r]     = (logf(ss[0]) + m) - row[t];
        g_correct[r] = (sai[0] == t) ? 1 : 0;
    }
}

// ---------------- final scalars ----------------
__global__ void finalize_kernel(const int* __restrict__ mask,
                                float* __restrict__ out, int n_scalars)
{
    __shared__ float s_lo[256], s_cn[256], s_tk[256];
    __shared__ int   s_seq[BSZ];
    const int tid = threadIdx.x;
    if (tid < BSZ) s_seq[tid] = 1;
    __syncthreads();

    float lo = 0.f, cn = 0.f, tk = 0.f;
    for (int r = tid; r < ROWS; r += 256) {
        const int mk  = mask[r];
        const int cor = g_correct[r];
        if (mk) {
            lo += g_nll[r];
            cn += 1.f;
            tk += (float)cor;
            if (!cor) atomicAnd(&s_seq[r / SEQ], 0);
        }
    }
    s_lo[tid] = lo; s_cn[tid] = cn; s_tk[tid] = tk;
    __syncthreads();

    for (int off = 128; off > 0; off >>= 1) {
        if (tid < off) {
            s_lo[tid] += s_lo[tid + off];
            s_cn[tid] += s_cn[tid + off];
            s_tk[tid] += s_tk[tid + off];
        }
        __syncthreads();
    }

    if (tid == 0) {
        const float nvalid = s_cn[0];
        if (n_scalars >= 1) out[0] = s_lo[0] / nvalid;
        if (n_scalars >= 2) out[1] = s_tk[0] / nvalid;
        if (n_scalars >= 3) {
            float sacc = 0.f;
            for (int b = 0; b < BSZ; b++) sacc += (float)s_seq[b];
            out[2] = sacc / (float)BSZ;
        }
    }
}

// ---------------- entry ----------------
extern "C" void kernel_launch(void* const* d_in, const int* in_sizes, int n_in,
                              void* d_out, int out_size)
{
    const float*     logits = (const float*)d_in[0];
    const long long* target = (const long long*)d_in[1];
    const int*       mask   = (const int*)d_in[2];
    const float*     W      = (const float*)d_in[3];

    float* out = (float*)d_out;
    const long long NTOK = (long long)ROWS * VOCAB;

    float* tokens;
    float* scalars;
    int n_scalars;
    if ((long long)out_size >= NTOK + 3) {
        scalars = out;
        n_scalars = (int)((long long)out_size - NTOK);
        if (n_scalars > 3) n_scalars = 3;
        tokens = out + n_scalars;
    } else if ((long long)out_size >= NTOK) {
        scalars = out; n_scalars = 0; tokens = out;
    } else {
        return;
    }

    cudaFuncSetAttribute(gemm_mma_kernel,
                         cudaFuncAttributeMaxDynamicSharedMemorySize, SMEM_TOTAL);

    convertA_kernel<<<2048, 256>>>(logits);
    convertW_kernel<<<16384, 256>>>(W);

    dim3 grid(ROWS / BM, NPAD / BN);   // (32, 197), m fastest
    gemm_mma_kernel<<<grid, 256, SMEM_TOTAL>>>(tokens);

    row_stats_kernel<<<ROWS, 256>>>(tokens, target);
    if (n_scalars > 0)
        finalize_kernel<<<1, 256>>>(mask, scalars, n_scalars);
}

// round 10
// speedup vs baseline: 5.4418x; 2.2020x over previous
#include <cuda_runtime.h>
#include <cuda_fp16.h>
#include <math.h>
#include <stdint.h>

// ---------------- Problem constants ----------------
#define VOCAB  50257
#define DMODEL 1024
#define SEQ    2048
#define BSZ    2
#define ROWS   (BSZ * SEQ)     // 4096
#define NPAD   50432           // VOCAB padded to multiple of 256 (197*256)

// ---------------- GEMM tiling ----------------
#define BM 128
#define BN 256
#define KC 64                          // k-chunk (fp16 elems) = 128 bytes/row
#define NCHUNK (DMODEL / KC)           // 16
#define ROWB 144                       // smem row stride bytes (128 data + 16 pad)
#define TILE_A (128 * ROWB)            // 18432
#define TILE_W (256 * ROWB)            // 36864
#define STAGE_B (TILE_A + TILE_W)      // 55296
#define NSTAGE 3
#define SMEM_TOTAL (NSTAGE * STAGE_B)  // 165888

// ---------------- Scratch (__device__ globals; no allocs allowed) ----------------
__device__ __half g_Ah[ROWS * DMODEL];   // 8 MB
__device__ __half g_Wh[NPAD * DMODEL];   // 103 MB
__device__ float g_nll[ROWS];
__device__ int   g_correct[ROWS];

// ---------------- PTX helpers (baseline sm_80+ features only) ----------------
__device__ __forceinline__ uint32_t smem_u32(const void* p) {
    uint32_t a;
    asm("{ .reg .u64 t; cvta.to.shared.u64 t, %1; cvt.u32.u64 %0, t; }" : "=r"(a) : "l"(p));
    return a;
}
#define CPASYNC16(dst, src) \
    asm volatile("cp.async.cg.shared.global [%0], [%1], 16;\n" :: "r"(dst), "l"(src) : "memory")
#define CPCOMMIT() asm volatile("cp.async.commit_group;\n" ::: "memory")
#define CPWAIT1()  asm volatile("cp.async.wait_group 1;\n" ::: "memory")
#define CPWAIT0()  asm volatile("cp.async.wait_group 0;\n" ::: "memory")

#define LDSM4(r, a) \
    asm volatile("ldmatrix.sync.aligned.m8n8.x4.shared.b16 {%0,%1,%2,%3}, [%4];" \
                 : "=r"((r)[0]), "=r"((r)[1]), "=r"((r)[2]), "=r"((r)[3]) : "r"(a))

#define MMA_FP16(c, a, b) \
    asm volatile("mma.sync.aligned.m16n8k16.row.col.f32.f16.f16.f32 " \
                 "{%0,%1,%2,%3}, {%4,%5,%6,%7}, {%8,%9}, {%0,%1,%2,%3};" \
                 : "+f"((c)[0]), "+f"((c)[1]), "+f"((c)[2]), "+f"((c)[3]) \
                 : "r"((a)[0]), "r"((a)[1]), "r"((a)[2]), "r"((a)[3]), \
                   "r"((b)[0]), "r"((b)[1]))

// ---------------- fp32 -> fp16 (RNE) ----------------
__global__ void convertA_kernel(const float* __restrict__ A) {
    int n = ROWS * DMODEL;
    for (int i = blockIdx.x * blockDim.x + threadIdx.x; i < n; i += gridDim.x * blockDim.x)
        g_Ah[i] = __float2half_rn(A[i]);
}
__global__ void convertW_kernel(const float* __restrict__ W) {
    int n = NPAD * DMODEL;
    for (int i = blockIdx.x * blockDim.x + threadIdx.x; i < n; i += gridDim.x * blockDim.x) {
        int row = i >> 10;
        g_Wh[i] = __float2half_rn((row < VOCAB) ? W[i] : 0.f);
    }
}

// ---------------- fp16 GEMM via mma.sync (HMMA) ----------------
// C[m,n] = sum_k A[m,k] * W[n,k]
// CTA: 128x256; 8 warps (2 m x 4 n); warp tile 64x64; 3-stage cp.async pipeline.
__global__ __launch_bounds__(256, 1)
void gemm_mma_kernel(float* __restrict__ C)
{
    extern __shared__ char smem[];
    const uint32_t sb = smem_u32(smem);
    const int tid    = threadIdx.x;
    const int lane   = tid & 31;
    const int wid    = tid >> 5;
    const int warp_m = wid >> 2;         // 0..1 -> 64 rows
    const int warp_n = wid & 3;          // 0..3 -> 64 cols
    const int m0     = blockIdx.x * BM;  // m fastest => W tile L2 reuse
    const int n0     = blockIdx.y * BN;

    const char* pA = (const char*)g_Ah + (size_t)m0 * (DMODEL * 2);
    const char* pW = (const char*)g_Wh + (size_t)n0 * (DMODEL * 2);

    // ---- stage loader: 3072 x 16B cp.async, 12 per thread.
    // rows have 8 x 16B segments (128 data bytes), stride ROWB=144.
    //   q 0-3 : A tile (128 rows x 8 segs = 1024 ops)
    //   q 4-11: W tile (256 rows x 8 segs = 2048 ops)
    auto load_chunk = [&](int s, int k) {
        const uint32_t base = sb + s * STAGE_B;
        const size_t koff = (size_t)k * (KC * 2);      // 128 bytes
#pragma unroll
        for (int q = 0; q < 12; q++) {
            const int i = tid + q * 256;
            const char* src;
            uint32_t dstBase;
            int j;
            if (i < 1024) { src = pA; dstBase = base;          j = i; }
            else          { src = pW; dstBase = base + TILE_A; j = i - 1024; }
            const int row = j >> 3;
            const int c16 = (j & 7) << 4;
            CPASYNC16(dstBase + row * ROWB + c16,
                      src + (size_t)row * 2048 + koff + c16);
        }
        CPCOMMIT();
    };

    float acc[4][8][4];                       // [m-tile][n-tile][frag]
#pragma unroll
    for (int i = 0; i < 4; i++)
#pragma unroll
        for (int j = 0; j < 8; j++)
#pragma unroll
            for (int e = 0; e < 4; e++) acc[i][j][e] = 0.f;

    load_chunk(0, 0);
    load_chunk(1, 1);

    // in-tile ldmatrix lane offsets (mapping validated R6/R9); ROWB=144 keeps
    // the 8-row phase conflict-free: group(r) = (9r + c) & 7 is a permutation.
    const uint32_t aLaneOff = (uint32_t)(lane & 15) * ROWB + (uint32_t)(lane >> 4) * 16;
    const uint32_t bLaneOff = ((uint32_t)((lane >> 4) << 3) + (lane & 7)) * ROWB +
                              (uint32_t)((lane >> 3) & 1) * 16;

    for (int k = 0; k < NCHUNK; k++) {
        const int s = k % NSTAGE;
        if (k < NCHUNK - 1) CPWAIT1(); else CPWAIT0();
        __syncthreads();

        if (k + 2 < NCHUNK) load_chunk((k + 2) % NSTAGE, k + 2);

        const uint32_t base = sb + s * STAGE_B;
        const uint32_t aT = base + (warp_m * 64) * ROWB + aLaneOff;
        const uint32_t bT = base + TILE_A + (warp_n * 64) * ROWB + bLaneOff;

#pragma unroll
        for (int ks = 0; ks < 4; ks++) {               // 4 x k16 per 64-chunk
            const uint32_t kb = ks * 32;               // 32B per k16 (fp16)
            uint32_t ah[4][4], bh[8][2];
#pragma unroll
            for (int ti = 0; ti < 4; ti++)
                LDSM4(ah[ti], aT + ti * (16 * ROWB) + kb);
#pragma unroll
            for (int nb = 0; nb < 4; nb++) {
                uint32_t r[4];
                LDSM4(r, bT + nb * (16 * ROWB) + kb);
                bh[2 * nb][0] = r[0]; bh[2 * nb][1] = r[1];
                bh[2 * nb + 1][0] = r[2]; bh[2 * nb + 1][1] = r[3];
            }
#pragma unroll
            for (int ti = 0; ti < 4; ti++)
#pragma unroll
                for (int ni = 0; ni < 8; ni++)
                    MMA_FP16(acc[ti][ni], ah[ti], bh[ni]);
        }
        __syncthreads();   // all warps done with stage s before it is reloaded
    }

    // ---- epilogue: regs -> gmem ----
    const int mrow = m0 + warp_m * 64 + (lane >> 2);
    const int ncol = n0 + warp_n * 64 + 2 * (lane & 3);
#pragma unroll
    for (int ti = 0; ti < 4; ti++) {
#pragma unroll
        for (int half = 0; half < 2; half++) {
            const int r = mrow + ti * 16 + half * 8;
            float* crow = C + (size_t)r * VOCAB;
#pragma unroll
            for (int ni = 0; ni < 8; ni++) {
                const int c = ncol + ni * 8;
                if (c < VOCAB)     crow[c]     = acc[ti][ni][half * 2];
                if (c + 1 < VOCAB) crow[c + 1] = acc[ti][ni][half * 2 + 1];
            }
        }
    }
}

// ---------------- per-row max/argmax + sum-exp (two-pass) ----------------
__global__ void row_stats_kernel(const float* __restrict__ C,
                                 const long long* __restrict__ target)
{
    const int r   = blockIdx.x;
    const int tid = threadIdx.x;
    const float* row = C + (size_t)r * VOCAB;

    // float4 alignment derived from the ACTUAL pointer (C sits at +3 floats).
    const int lead  = (int)((4 - (((uintptr_t)row >> 2) & 3)) & 3);
    const int n4    = (VOCAB - lead) >> 2;
    const int tail0 = lead + n4 * 4;
    const float4* row4 = (const float4*)(row + lead);

    // ---- pass 1: max + argmax ----
    float av = -INFINITY; int ai = 0;
    if (tid < lead) { float x = row[tid]; if (x > av) { av = x; ai = tid; } }
    for (int j = tid; j < n4; j += 256) {
        const float4 v = row4[j];
        const int i = lead + 4 * j;
        if (v.x > av) { av = v.x; ai = i; }
        if (v.y > av) { av = v.y; ai = i + 1; }
        if (v.z > av) { av = v.z; ai = i + 2; }
        if (v.w > av) { av = v.w; ai = i + 3; }
    }
    for (int i = tail0 + tid; i < VOCAB; i += 256) {
        const float x = row[i];
        if (x > av) { av = x; ai = i; }
    }

    __shared__ float sav[256];
    __shared__ int   sai[256];
    __shared__ float ss[256];
    sav[tid] = av; sai[tid] = ai;
    __syncthreads();
    for (int off = 128; off > 0; off >>= 1) {
        if (tid < off) {
            const float a2 = sav[tid + off]; const int i2 = sai[tid + off];
            if (a2 > sav[tid] || (a2 == sav[tid] && i2 < sai[tid])) {
                sav[tid] = a2; sai[tid] = i2;
            }
        }
        __syncthreads();
    }
    const float m = sav[0];

    // ---- pass 2: sum exp(x - m) (re-read; mostly L2 hits) ----
    float s = 0.f;
    if (tid < lead) s += __expf(row[tid] - m);
    for (int j = tid; j < n4; j += 256) {
        const float4 v = row4[j];
        s += __expf(v.x - m) + __expf(v.y - m) + __expf(v.z - m) + __expf(v.w - m);
    }
    for (int i = tail0 + tid; i < VOCAB; i += 256) s += __expf(row[i] - m);

    ss[tid] = s;
    __syncthreads();
    for (int off = 128; off > 0; off >>= 1) {
        if (tid < off) ss[tid] += ss[tid + off];
        __syncthreads();
    }

    if (tid == 0) {
        const int t = (int)target[r];
        g_nll[r]     = (logf(ss[0]) + m) - row[t];
        g_correct[r] = (sai[0] == t) ? 1 : 0;
    }
}

// ---------------- final scalars ----------------
__global__ void finalize_kernel(const int* __restrict__ mask,
                                float* __restrict__ out, int n_scalars)
{
    __shared__ float s_lo[256], s_cn[256], s_tk[256];
    __shared__ int   s_seq[BSZ];
    const int tid = threadIdx.x;
    if (tid < BSZ) s_seq[tid] = 1;
    __syncthreads();

    float lo = 0.f, cn = 0.f, tk = 0.f;
    for (int r = tid; r < ROWS; r += 256) {
        const int mk  = mask[r];
        const int cor = g_correct[r];
        if (mk) {
            lo += g_nll[r];
            cn += 1.f;
            tk += (float)cor;
            if (!cor) atomicAnd(&s_seq[r / SEQ], 0);
        }
    }
    s_lo[tid] = lo; s_cn[tid] = cn; s_tk[tid] = tk;
    __syncthreads();

    for (int off = 128; off > 0; off >>= 1) {
        if (tid < off) {
            s_lo[tid] += s_lo[tid + off];
            s_cn[tid] += s_cn[tid + off];
            s_tk[tid] += s_tk[tid + off];
        }
        __syncthreads();
    }

    if (tid == 0) {
        const float nvalid = s_cn[0];
        if (n_scalars >= 1) out[0] = s_lo[0] / nvalid;
        if (n_scalars >= 2) out[1] = s_tk[0] / nvalid;
        if (n_scalars >= 3) {
            float sacc = 0.f;
            for (int b = 0; b < BSZ; b++) sacc += (float)s_seq[b];
            out[2] = sacc / (float)BSZ;
        }
    }
}

// ---------------- entry ----------------
extern "C" void kernel_launch(void* const* d_in, const int* in_sizes, int n_in,
                              void* d_out, int out_size)
{
    const float*     logits = (const float*)d_in[0];
    const long long* target = (const long long*)d_in[1];
    const int*       mask   = (const int*)d_in[2];
    const float*     W      = (const float*)d_in[3];

    float* out = (float*)d_out;
    const long long NTOK = (long long)ROWS * VOCAB;

    float* tokens;
    float* scalars;
    int n_scalars;
    if ((long long)out_size >= NTOK + 3) {
        scalars = out;
        n_scalars = (int)((long long)out_size - NTOK);
        if (n_scalars > 3) n_scalars = 3;
        tokens = out + n_scalars;
    } else if ((long long)out_size >= NTOK) {
        scalars = out; n_scalars = 0; tokens = out;
    } else {
        return;
    }

    cudaFuncSetAttribute(gemm_mma_kernel,
                         cudaFuncAttributeMaxDynamicSharedMemorySize, SMEM_TOTAL);

    convertA_kernel<<<2048, 256>>>(logits);
    convertW_kernel<<<16384, 256>>>(W);

    dim3 grid(ROWS / BM, NPAD / BN);   // (32, 197), m fastest
    gemm_mma_kernel<<<grid, 256, SMEM_TOTAL>>>(tokens);

    row_stats_kernel<<<ROWS, 256>>>(tokens, target);
    if (n_scalars > 0)
        finalize_kernel<<<1, 256>>>(mask, scalars, n_scalars);
}